// round 10
// baseline (speedup 1.0000x reference)
#include <cuda_runtime.h>
#include <cuda_fp16.h>
#include <mma.h>
#include <cstdint>

using namespace nvcuda;

#define T_TOK 4096
#define DDIM  768
#define IDIM  2048
#define NEXP  8
#define TM    128
#define NTILES 40
#define PADROWS (NTILES*TM)
#define KC    64             // halves per K chunk
#define LDH   72             // padded row length (halves): 144B rows, conflict-free ldmatrix
#define LDST  132            // gemm1 fp32 staging stride (128 cols)
#define LDST3 260            // gemm2 fp32 staging stride (256 cols): %4==0, row %16B==0
#define A_BYTES (128 * LDH * 2)          // 18432
#define B_BYTES (256 * LDH * 2)          // 36864 (two stacked 128-row tiles)
#define STAGE_BYTES (A_BYTES + B_BYTES)  // 55296
#define NSTAGE 3
#define GSMEM (NSTAGE * STAGE_BYTES)     // 165888 -> 1 CTA/SM (8 warps)

// ---------------- device-global scratch (tiled layouts, no allocation) ------
__device__ int    g_perm[PADROWS];
__device__ int    g_tile_expert[NTILES];
// [e][y:32][kc:12][r:128][72]  rows interleaved [G0-31|U0-31|G32-63|U32-63]
__device__ __half g_wgu[(size_t)NEXP * 32 * 12 * 128 * LDH];
// [e][y:6][kc:32][r:128][72]
__device__ __half g_wdt[(size_t)NEXP * 6 * 32 * 128 * LDH];
// [tile:40][kc:12][r:128][72]
__device__ __half g_xt [(size_t)NTILES * 12 * 128 * LDH];
// [tile:40][kc:32][r:128][72]
__device__ __half g_ht [(size_t)NTILES * 32 * 128 * LDH];
// split-K partials, permuted row order: [z:2][PADROWS][768]
__device__ float  g_gp [(size_t)2 * PADROWS * DDIM];

// ---------------- PTX helpers -----------------------------------------------
__device__ __forceinline__ uint32_t smem_u32(const void* p) {
    uint32_t a;
    asm("{ .reg .u64 t; cvta.to.shared.u64 t, %1; cvt.u32.u64 %0, t; }" : "=r"(a) : "l"(p));
    return a;
}
__device__ __forceinline__ void mbar_init(uint32_t a) {
    asm volatile("mbarrier.init.shared.b64 [%0], 1;" :: "r"(a) : "memory");
}
__device__ __forceinline__ void mbar_expect_tx(uint32_t a, uint32_t bytes) {
    asm volatile("mbarrier.arrive.expect_tx.shared.b64 _, [%0], %1;" :: "r"(a), "r"(bytes) : "memory");
}
__device__ __forceinline__ void mbar_wait(uint32_t mbar, int parity) {
    asm volatile(
        "{\n\t.reg .pred P;\n\t"
        "WL_%=:\n\t"
        "mbarrier.try_wait.parity.acquire.cta.shared::cta.b64 P, [%0], %1, 0x989680;\n\t"
        "@P bra.uni WD_%=;\n\t"
        "bra.uni WL_%=;\n\t"
        "WD_%=:\n\t}"
        :: "r"(mbar), "r"(parity) : "memory");
}
__device__ __forceinline__ void bulk_g2s(uint32_t dst, const void* src, uint32_t bytes, uint32_t mbar) {
    asm volatile(
        "cp.async.bulk.shared::cluster.global.mbarrier::complete_tx::bytes [%0], [%1], %2, [%3];"
        :: "r"(dst), "l"(src), "r"(bytes), "r"(mbar) : "memory");
}
#define FENCE_ASYNC() asm volatile("fence.proxy.async.shared::cta;" ::: "memory")

// ---------------------------------------------------------------------------
// Routing (int64/int32 safe)
// ---------------------------------------------------------------------------
__global__ void route_kernel(const void* __restrict__ pos) {
    __shared__ int cnt[NEXP], off[NEXP], cur[NEXP];
    __shared__ int s_not64;
    const int tid = threadIdx.x;
    if (tid < NEXP) { cnt[tid] = 0; cur[tid] = 0; }
    if (tid == 0) s_not64 = 0;
    __syncthreads();
    const unsigned long long* pl = (const unsigned long long*)pos;
    for (int i = tid; i < T_TOK / 2; i += blockDim.x)
        if (pl[i] > 7ULL) s_not64 = 1;
    __syncthreads();
    const int is64 = !s_not64;
    const long long* p64 = (const long long*)pos;
    const int*       p32 = (const int*)pos;
    for (int t = tid; t < T_TOK; t += blockDim.x) {
        int e = is64 ? (int)p64[t] : p32[t];
        atomicAdd(&cnt[e], 1);
    }
    for (int i = tid; i < PADROWS; i += blockDim.x) g_perm[i] = -1;
    __syncthreads();
    if (tid == 0) {
        int o = 0;
        for (int e = 0; e < NEXP; e++) {
            off[e] = o;
            int nt = (cnt[e] + TM - 1) / TM;
            for (int k = 0; k < nt; k++) g_tile_expert[o / TM + k] = e;
            o += nt * TM;
        }
        for (int tl = o / TM; tl < NTILES; tl++) g_tile_expert[tl] = -1;
    }
    __syncthreads();
    for (int t = tid; t < T_TOK; t += blockDim.x) {
        int e = is64 ? (int)p64[t] : p32[t];
        int p = off[e] + atomicAdd(&cur[e], 1);
        g_perm[p] = t;
    }
}

// ---------------------------------------------------------------------------
// cvt: fp32 -> fp16 into tiled layouts (dst offset == idx*8 halves by design)
// ---------------------------------------------------------------------------
__device__ __forceinline__ uint4 cvt8(const float* src) {
    float4 v0 = *(const float4*)src;
    float4 v1 = *(const float4*)(src + 4);
    __half2 h0 = __floats2half2_rn(v0.x, v0.y), h1 = __floats2half2_rn(v0.z, v0.w);
    __half2 h2 = __floats2half2_rn(v1.x, v1.y), h3 = __floats2half2_rn(v1.z, v1.w);
    uint4 o;
    o.x = *(uint32_t*)&h0; o.y = *(uint32_t*)&h1;
    o.z = *(uint32_t*)&h2; o.w = *(uint32_t*)&h3;
    return o;
}

__global__ void cvt_wgu(const float* __restrict__ gw, const float* __restrict__ uw) {
    const int TOT = NEXP * 32 * 12 * 128 * 9;
    int idx = blockIdx.x * 256 + threadIdx.x;
    if (idx >= TOT) return;
    int c8 = idx % 9; int t1 = idx / 9;
    int r  = t1 % 128; t1 /= 128;
    int kc = t1 % 12;  t1 /= 12;
    int y  = t1 % 32;  int e = t1 / 32;
    uint4 o = make_uint4(0, 0, 0, 0);
    if (c8 < 8) {
        int q = r & 63;
        int wrow = y * 64 + (r >> 6) * 32 + (q & 31);
        const float* src = ((q < 32) ? gw : uw) + ((size_t)e * IDIM + wrow) * DDIM + kc * 64 + c8 * 8;
        o = cvt8(src);
    }
    *(uint4*)(g_wgu + (size_t)idx * 8) = o;
}

__global__ void cvt_wd(const float* __restrict__ dw) {
    const int TOT = NEXP * 6 * 32 * 128 * 9;
    int idx = blockIdx.x * 256 + threadIdx.x;
    if (idx >= TOT) return;
    int c8 = idx % 9; int t1 = idx / 9;
    int r  = t1 % 128; t1 /= 128;
    int kc = t1 % 32;  t1 /= 32;
    int y  = t1 % 6;   int e = t1 / 6;
    uint4 o = make_uint4(0, 0, 0, 0);
    if (c8 < 8) {
        const float* src = dw + ((size_t)e * DDIM + y * 128 + r) * IDIM + kc * 64 + c8 * 8;
        o = cvt8(src);
    }
    *(uint4*)(g_wdt + (size_t)idx * 8) = o;
}

__global__ void cvt_x(const float* __restrict__ x) {   // run AFTER route
    const int TOT = NTILES * 12 * 128 * 9;
    int idx = blockIdx.x * 256 + threadIdx.x;
    if (idx >= TOT) return;
    int c8 = idx % 9; int t1 = idx / 9;
    int r  = t1 % 128; t1 /= 128;
    int kc = t1 % 12;  int tile = t1 / 12;
    uint4 o = make_uint4(0, 0, 0, 0);
    int t = g_perm[tile * TM + r];
    if (c8 < 8 && t >= 0)
        o = cvt8(x + (size_t)t * DDIM + kc * 64 + c8 * 8);
    *(uint4*)(g_xt + (size_t)idx * 8) = o;
}

// ---------------------------------------------------------------------------
// GEMM1: 128x256 CTA tile (two 128-row G|U weight tiles), 8 warps (2x4),
// warp tile 64x64, 3-stage bulk pipeline, 1 CTA/SM.
// acc[i][j<2] = G, acc[i][j>=2] = matching U cols -> in-register silu(G)*U.
// ---------------------------------------------------------------------------
__global__ __launch_bounds__(256, 1) __cluster_dims__(1, 1, 1) void gemm1_kernel() {
    const int tile = blockIdx.x;
    const int e = g_tile_expert[tile];
    if (e < 0) return;
    const int by = blockIdx.y;         // covers y_eff = 2*by, 2*by+1

    extern __shared__ __align__(128) char sh[];
    __shared__ __align__(8) unsigned long long mbars[NSTAGE];
    const uint32_t sb = smem_u32(sh);
    const uint32_t mb0 = smem_u32(mbars);
    const int tid = threadIdx.x;

    if (tid == 0)
        for (int s = 0; s < NSTAGE; s++) mbar_init(mb0 + 8 * s);
    __syncthreads();

    const __half* Asrc  = g_xt  + (size_t)tile * 12 * 128 * LDH;
    const __half* B0src = g_wgu + (size_t)((e * 32 + 2 * by) * 12) * 128 * LDH;
    const __half* B1src = g_wgu + (size_t)((e * 32 + 2 * by + 1) * 12) * 128 * LDH;

    const int NK = DDIM / KC;  // 12
    auto issue = [&](int s, int kc) {
        mbar_expect_tx(mb0 + 8 * s, STAGE_BYTES);
        uint32_t base = sb + s * STAGE_BYTES;
        bulk_g2s(base,                      Asrc  + (size_t)kc * 128 * LDH, A_BYTES, mb0 + 8 * s);
        bulk_g2s(base + A_BYTES,            B0src + (size_t)kc * 128 * LDH, A_BYTES, mb0 + 8 * s);
        bulk_g2s(base + A_BYTES + A_BYTES,  B1src + (size_t)kc * 128 * LDH, A_BYTES, mb0 + 8 * s);
    };
    if (tid == 0) {
        FENCE_ASYNC();
        for (int s = 0; s < NSTAGE; s++) issue(s, s);
    }

    const int wid = tid >> 5;
    const int wm = wid >> 2, wn = wid & 3;       // 2 x 4 warp grid
    const int bT = wn >> 1, wn2 = wn & 1;        // which 128-row B tile, which half

    wmma::fragment<wmma::accumulator, 16, 16, 16, float> acc[4][4];
#pragma unroll
    for (int i = 0; i < 4; i++)
#pragma unroll
        for (int j = 0; j < 4; j++) wmma::fill_fragment(acc[i][j], 0.0f);

    for (int kc = 0; kc < NK; kc++) {
        const int s = kc % NSTAGE;
        mbar_wait(mb0 + 8 * s, (kc / NSTAGE) & 1);
        const __half* A = (const __half*)(sh + s * STAGE_BYTES);
        const __half* B = A + 128 * LDH;
#pragma unroll
        for (int ks = 0; ks < KC / 16; ks++) {
            wmma::fragment<wmma::matrix_a, 16, 16, 16, __half, wmma::row_major> fa[4];
            wmma::fragment<wmma::matrix_b, 16, 16, 16, __half, wmma::col_major> fb[4];
#pragma unroll
            for (int i = 0; i < 4; i++)
                wmma::load_matrix_sync(fa[i], A + (wm * 64 + i * 16) * LDH + ks * 16, LDH);
#pragma unroll
            for (int j = 0; j < 4; j++)
                wmma::load_matrix_sync(fb[j], B + (bT * 128 + wn2 * 64 + j * 16) * LDH + ks * 16, LDH);
#pragma unroll
            for (int i = 0; i < 4; i++)
#pragma unroll
                for (int j = 0; j < 4; j++)
                    wmma::mma_sync(acc[i][j], fa[i], fb[j], acc[i][j]);
        }
        __syncthreads();
        int kn = kc + NSTAGE;
        if (kn < NK && tid == 0) issue(s, kn);
    }

    // In-register silu(G)*U, stage fp32 h (128 x 128, stride 132), write fp16.
    float* st = (float*)sh;   // 128*132*4 = 67584 <= 165888
    __syncthreads();
#pragma unroll
    for (int i = 0; i < 4; i++)
#pragma unroll
        for (int jj = 0; jj < 2; jj++) {
#pragma unroll
            for (int el = 0; el < acc[i][jj].num_elements; el++) {
                float g = acc[i][jj].x[el];
                float u = acc[i][jj + 2].x[el];
                acc[i][jj].x[el] = (g / (1.0f + __expf(-g))) * u;
            }
            wmma::store_matrix_sync(st + (wm * 64 + i * 16) * LDST + bT * 64 + wn2 * 32 + jj * 16,
                                    acc[i][jj], LDST, wmma::mem_row_major);
        }
    __syncthreads();

#pragma unroll
    for (int it = 0; it < 32; it++) {            // 2 halves x 128 rows x 32 half2
        int p = tid + 256 * it;
        int half = p >> 12, r = (p >> 5) & 127, c2 = p & 31;
        __half* hdst = g_ht + (size_t)(tile * 32 + 2 * by + half) * 128 * LDH;
        float h0 = st[r * LDST + half * 64 + c2 * 2];
        float h1 = st[r * LDST + half * 64 + c2 * 2 + 1];
        __half2 hv = __floats2half2_rn(h0, h1);
        *(uint32_t*)(hdst + r * LDH + c2 * 2) = *(uint32_t*)&hv;
    }
}

// ---------------------------------------------------------------------------
// GEMM2: split-K, 128x256 CTA tile, 8 warps (2x4), warp 64x64, 3 stages.
// grid (40, 3, 2): y covers 256 output cols, z halves K.
// ---------------------------------------------------------------------------
__global__ __launch_bounds__(256, 1) __cluster_dims__(1, 1, 1) void gemm2_kernel() {
    const int tile = blockIdx.x;
    const int e = g_tile_expert[tile];
    if (e < 0) return;
    const int y = blockIdx.y;
    const int z = blockIdx.z;

    extern __shared__ __align__(128) char sh[];
    __shared__ __align__(8) unsigned long long mbars[NSTAGE];
    const uint32_t sb = smem_u32(sh);
    const uint32_t mb0 = smem_u32(mbars);
    const int tid = threadIdx.x;

    if (tid == 0)
        for (int s = 0; s < NSTAGE; s++) mbar_init(mb0 + 8 * s);
    __syncthreads();

    const __half* Asrc  = g_ht  + (size_t)(tile * 32 + z * 16) * 128 * LDH;
    const __half* B0src = g_wdt + (size_t)((e * 6 + 2 * y) * 32 + z * 16) * 128 * LDH;
    const __half* B1src = g_wdt + (size_t)((e * 6 + 2 * y + 1) * 32 + z * 16) * 128 * LDH;

    const int NK = 16;
    auto issue = [&](int s, int kc) {
        mbar_expect_tx(mb0 + 8 * s, STAGE_BYTES);
        uint32_t base = sb + s * STAGE_BYTES;
        bulk_g2s(base,                     Asrc  + (size_t)kc * 128 * LDH, A_BYTES, mb0 + 8 * s);
        bulk_g2s(base + A_BYTES,           B0src + (size_t)kc * 128 * LDH, A_BYTES, mb0 + 8 * s);
        bulk_g2s(base + A_BYTES + A_BYTES, B1src + (size_t)kc * 128 * LDH, A_BYTES, mb0 + 8 * s);
    };
    if (tid == 0) {
        FENCE_ASYNC();
        for (int s = 0; s < NSTAGE; s++) issue(s, s);
    }

    const int wid = tid >> 5;
    const int wm = wid >> 2, wn = wid & 3;
    const int bT = wn >> 1, wn2 = wn & 1;

    wmma::fragment<wmma::accumulator, 16, 16, 16, float> acc[4][4];
#pragma unroll
    for (int i = 0; i < 4; i++)
#pragma unroll
        for (int j = 0; j < 4; j++) wmma::fill_fragment(acc[i][j], 0.0f);

    for (int kc = 0; kc < NK; kc++) {
        const int s = kc % NSTAGE;
        mbar_wait(mb0 + 8 * s, (kc / NSTAGE) & 1);
        const __half* A = (const __half*)(sh + s * STAGE_BYTES);
        const __half* B = A + 128 * LDH;
#pragma unroll
        for (int ks = 0; ks < KC / 16; ks++) {
            wmma::fragment<wmma::matrix_a, 16, 16, 16, __half, wmma::row_major> fa[4];
            wmma::fragment<wmma::matrix_b, 16, 16, 16, __half, wmma::col_major> fb[4];
#pragma unroll
            for (int i = 0; i < 4; i++)
                wmma::load_matrix_sync(fa[i], A + (wm * 64 + i * 16) * LDH + ks * 16, LDH);
#pragma unroll
            for (int j = 0; j < 4; j++)
                wmma::load_matrix_sync(fb[j], B + (bT * 128 + wn2 * 64 + j * 16) * LDH + ks * 16, LDH);
#pragma unroll
            for (int i = 0; i < 4; i++)
#pragma unroll
                for (int j = 0; j < 4; j++)
                    wmma::mma_sync(acc[i][j], fa[i], fb[j], acc[i][j]);
        }
        __syncthreads();
        int kn = kc + NSTAGE;
        if (kn < NK && tid == 0) issue(s, kn);
    }

    // Stage fp32 (128 x 260), write partial (permuted order, no scatter).
    float* st = (float*)sh;   // 128*260*4 = 133120 <= 165888
    __syncthreads();
#pragma unroll
    for (int i = 0; i < 4; i++)
#pragma unroll
        for (int j = 0; j < 4; j++)
            wmma::store_matrix_sync(st + (wm * 64 + i * 16) * LDST3 + bT * 128 + wn2 * 64 + j * 16,
                                    acc[i][j], LDST3, wmma::mem_row_major);
    __syncthreads();

    float* dst = g_gp + ((size_t)z * PADROWS + tile * 128) * DDIM + y * 256;
#pragma unroll
    for (int it = 0; it < 32; it++) {            // 128 rows x 64 float4
        int p = tid + 256 * it;
        int r = p >> 6, c4 = (p & 63) * 4;
        *(float4*)(dst + (size_t)r * DDIM + c4) = *(float4*)&st[r * LDST3 + c4];
    }
}

// ---------------------------------------------------------------------------
// add partials + scatter to output
// ---------------------------------------------------------------------------
__global__ void add_kernel(float* __restrict__ out) {
    int idx = blockIdx.x * 256 + threadIdx.x;
    if (idx >= PADROWS * (DDIM / 4)) return;
    int p = idx / (DDIM / 4), c4 = (idx % (DDIM / 4)) * 4;
    int t = g_perm[p];
    if (t < 0) return;
    const float* a = g_gp + (size_t)p * DDIM + c4;
    const float* b = g_gp + (size_t)(PADROWS + p) * DDIM + c4;
    float4 va = *(const float4*)a, vb = *(const float4*)b;
    float4 o = make_float4(va.x + vb.x, va.y + vb.y, va.z + vb.z, va.w + vb.w);
    *(float4*)(out + (size_t)t * DDIM + c4) = o;
}

// ---------------------------------------------------------------------------
extern "C" void kernel_launch(void* const* d_in, const int* in_sizes, int n_in,
                              void* d_out, int out_size) {
    const float* x   = (const float*)d_in[0];
    const void*  pos = d_in[1];
    // d_in[2] = behavior_index: unused
    const float* gw  = (const float*)d_in[3];
    const float* uw  = (const float*)d_in[4];
    const float* dw  = (const float*)d_in[5];
    float* out = (float*)d_out;

    static cudaStream_t s2 = nullptr, s3 = nullptr;
    static cudaEvent_t eFork = nullptr, eWgu = nullptr, eWd = nullptr;
    if (!s2) {
        cudaStreamCreateWithFlags(&s2, cudaStreamNonBlocking);
        cudaStreamCreateWithFlags(&s3, cudaStreamNonBlocking);
        cudaEventCreateWithFlags(&eFork, cudaEventDisableTiming);
        cudaEventCreateWithFlags(&eWgu, cudaEventDisableTiming);
        cudaEventCreateWithFlags(&eWd, cudaEventDisableTiming);
        cudaFuncSetAttribute(gemm1_kernel, cudaFuncAttributeMaxDynamicSharedMemorySize, GSMEM);
        cudaFuncSetAttribute(gemm2_kernel, cudaFuncAttributeMaxDynamicSharedMemorySize, GSMEM);
    }

    cudaEventRecord(eFork, 0);
    cudaStreamWaitEvent(s2, eFork, 0);
    cudaStreamWaitEvent(s3, eFork, 0);

    cvt_wgu<<<(NEXP * 32 * 12 * 128 * 9 + 255) / 256, 256, 0, s2>>>(gw, uw);
    cudaEventRecord(eWgu, s2);
    cvt_wd <<<(NEXP * 6 * 32 * 128 * 9 + 255) / 256, 256, 0, s3>>>(dw);
    cudaEventRecord(eWd, s3);

    route_kernel<<<1, 256>>>(pos);
    cvt_x<<<(NTILES * 12 * 128 * 9 + 255) / 256, 256>>>(x);

    cudaStreamWaitEvent(0, eWgu, 0);
    gemm1_kernel<<<dim3(NTILES, 16), 256, GSMEM>>>();

    cudaStreamWaitEvent(0, eWd, 0);
    gemm2_kernel<<<dim3(NTILES, 3, 2), 256, GSMEM>>>();
    add_kernel<<<(PADROWS * (DDIM / 4) + 255) / 256, 256>>>(out);
}

// round 11
// speedup vs baseline: 1.1250x; 1.1250x over previous
#include <cuda_runtime.h>
#include <cuda_fp16.h>
#include <mma.h>
#include <cstdint>

using namespace nvcuda;

#define T_TOK 4096
#define DDIM  768
#define IDIM  2048
#define NEXP  8
#define TM    128
#define NTILES 40
#define PADROWS (NTILES*TM)
#define KC    64             // halves per K chunk
#define LDH   72             // padded row length (halves): 144B rows, conflict-free ldmatrix
#define LDST  132            // fp32 staging stride (gemm2): %4==0, row %16B==0
#define LDST2 68             // fp32 staging stride (gemm1, 64 cols)
#define TILE_BYTES (128 * LDH * 2)       // 18432 B contiguous A or B chunk
#define STAGE_BYTES (2 * TILE_BYTES)     // 36864
#define NSTAGE 2
#define GSMEM (NSTAGE * STAGE_BYTES)     // 73728 -> 3 CTA/SM

// ---------------- device-global scratch (tiled layouts, no allocation) ------
__device__ int    g_perm[PADROWS];
__device__ int    g_tile_expert[NTILES];
// [e][y:32][kc:12][r:128][72]  rows interleaved [G0-31|U0-31|G32-63|U32-63]
__device__ __half g_wgu[(size_t)NEXP * 32 * 12 * 128 * LDH];
// [e][y:6][kc:32][r:128][72]
__device__ __half g_wdt[(size_t)NEXP * 6 * 32 * 128 * LDH];
// [tile:40][kc:12][r:128][72]
__device__ __half g_xt [(size_t)NTILES * 12 * 128 * LDH];
// [tile:40][kc:32][r:128][72]
__device__ __half g_ht [(size_t)NTILES * 32 * 128 * LDH];
// split-K partials, permuted row order: [z:2][PADROWS][768]
__device__ float  g_gp [(size_t)2 * PADROWS * DDIM];

// ---------------- PTX helpers -----------------------------------------------
__device__ __forceinline__ uint32_t smem_u32(const void* p) {
    uint32_t a;
    asm("{ .reg .u64 t; cvta.to.shared.u64 t, %1; cvt.u32.u64 %0, t; }" : "=r"(a) : "l"(p));
    return a;
}
__device__ __forceinline__ void mbar_init(uint32_t a) {
    asm volatile("mbarrier.init.shared.b64 [%0], 1;" :: "r"(a) : "memory");
}
__device__ __forceinline__ void mbar_expect_tx(uint32_t a, uint32_t bytes) {
    asm volatile("mbarrier.arrive.expect_tx.shared.b64 _, [%0], %1;" :: "r"(a), "r"(bytes) : "memory");
}
__device__ __forceinline__ void mbar_wait(uint32_t mbar, int parity) {
    asm volatile(
        "{\n\t.reg .pred P;\n\t"
        "WL_%=:\n\t"
        "mbarrier.try_wait.parity.acquire.cta.shared::cta.b64 P, [%0], %1, 0x989680;\n\t"
        "@P bra.uni WD_%=;\n\t"
        "bra.uni WL_%=;\n\t"
        "WD_%=:\n\t}"
        :: "r"(mbar), "r"(parity) : "memory");
}
__device__ __forceinline__ void bulk_g2s(uint32_t dst, const void* src, uint32_t bytes, uint32_t mbar) {
    asm volatile(
        "cp.async.bulk.shared::cluster.global.mbarrier::complete_tx::bytes [%0], [%1], %2, [%3];"
        :: "r"(dst), "l"(src), "r"(bytes), "r"(mbar) : "memory");
}
#define FENCE_ASYNC() asm volatile("fence.proxy.async.shared::cta;" ::: "memory")

// ---------------------------------------------------------------------------
// Routing (int64/int32 safe), 1024 threads
// ---------------------------------------------------------------------------
__global__ void route_kernel(const void* __restrict__ pos) {
    __shared__ int cnt[NEXP], off[NEXP], cur[NEXP];
    __shared__ int s_not64;
    const int tid = threadIdx.x;
    if (tid < NEXP) { cnt[tid] = 0; cur[tid] = 0; }
    if (tid == 0) s_not64 = 0;
    __syncthreads();
    const unsigned long long* pl = (const unsigned long long*)pos;
    for (int i = tid; i < T_TOK / 2; i += blockDim.x)
        if (pl[i] > 7ULL) s_not64 = 1;
    __syncthreads();
    const int is64 = !s_not64;
    const long long* p64 = (const long long*)pos;
    const int*       p32 = (const int*)pos;
    for (int t = tid; t < T_TOK; t += blockDim.x) {
        int e = is64 ? (int)p64[t] : p32[t];
        atomicAdd(&cnt[e], 1);
    }
    for (int i = tid; i < PADROWS; i += blockDim.x) g_perm[i] = -1;
    __syncthreads();
    if (tid == 0) {
        int o = 0;
        for (int e = 0; e < NEXP; e++) {
            off[e] = o;
            int nt = (cnt[e] + TM - 1) / TM;
            for (int k = 0; k < nt; k++) g_tile_expert[o / TM + k] = e;
            o += nt * TM;
        }
        for (int tl = o / TM; tl < NTILES; tl++) g_tile_expert[tl] = -1;
    }
    __syncthreads();
    for (int t = tid; t < T_TOK; t += blockDim.x) {
        int e = is64 ? (int)p64[t] : p32[t];
        int p = off[e] + atomicAdd(&cur[e], 1);
        g_perm[p] = t;
    }
}

// ---------------------------------------------------------------------------
// cvt: fp32 -> fp16 into tiled layouts
// ---------------------------------------------------------------------------
__device__ __forceinline__ uint4 cvt8(const float* src) {
    float4 v0 = *(const float4*)src;
    float4 v1 = *(const float4*)(src + 4);
    __half2 h0 = __floats2half2_rn(v0.x, v0.y), h1 = __floats2half2_rn(v0.z, v0.w);
    __half2 h2 = __floats2half2_rn(v1.x, v1.y), h3 = __floats2half2_rn(v1.z, v1.w);
    uint4 o;
    o.x = *(uint32_t*)&h0; o.y = *(uint32_t*)&h1;
    o.z = *(uint32_t*)&h2; o.w = *(uint32_t*)&h3;
    return o;
}

// y-half of the gate/up interleaved layout: y in [y0, y0+16)
__global__ void cvt_wgu(const float* __restrict__ gw, const float* __restrict__ uw, int y0) {
    const int TOT = NEXP * 16 * 12 * 128 * 9;
    int idx = blockIdx.x * 256 + threadIdx.x;
    if (idx >= TOT) return;
    int c8 = idx % 9; int t1 = idx / 9;
    int r  = t1 % 128; t1 /= 128;
    int kc = t1 % 12;  t1 /= 12;
    int y  = y0 + (t1 % 16);  int e = t1 / 16;
    uint4 o = make_uint4(0, 0, 0, 0);
    if (c8 < 8) {
        int q = r & 63;
        int wrow = y * 64 + (r >> 6) * 32 + (q & 31);
        const float* src = ((q < 32) ? gw : uw) + ((size_t)e * IDIM + wrow) * DDIM + kc * 64 + c8 * 8;
        o = cvt8(src);
    }
    size_t dst = ((((size_t)(e * 32 + y) * 12 + kc) * 128 + r) * 9 + c8) * 8;
    *(uint4*)(g_wgu + dst) = o;
}

__global__ void cvt_wd(const float* __restrict__ dw) {
    const int TOT = NEXP * 6 * 32 * 128 * 9;
    int idx = blockIdx.x * 256 + threadIdx.x;
    if (idx >= TOT) return;
    int c8 = idx % 9; int t1 = idx / 9;
    int r  = t1 % 128; t1 /= 128;
    int kc = t1 % 32;  t1 /= 32;
    int y  = t1 % 6;   int e = t1 / 6;
    uint4 o = make_uint4(0, 0, 0, 0);
    if (c8 < 8) {
        const float* src = dw + ((size_t)e * DDIM + y * 128 + r) * IDIM + kc * 64 + c8 * 8;
        o = cvt8(src);
    }
    *(uint4*)(g_wdt + (size_t)idx * 8) = o;
}

__global__ void cvt_x(const float* __restrict__ x) {   // run AFTER route
    const int TOT = NTILES * 12 * 128 * 9;
    int idx = blockIdx.x * 256 + threadIdx.x;
    if (idx >= TOT) return;
    int c8 = idx % 9; int t1 = idx / 9;
    int r  = t1 % 128; t1 /= 128;
    int kc = t1 % 12;  int tile = t1 / 12;
    uint4 o = make_uint4(0, 0, 0, 0);
    int t = g_perm[tile * TM + r];
    if (c8 < 8 && t >= 0)
        o = cvt8(x + (size_t)t * DDIM + kc * 64 + c8 * 8);
    *(uint4*)(g_xt + (size_t)idx * 8) = o;
}

// ---------------------------------------------------------------------------
// GEMM1: 128x128 CTA tile (64 G cols + 64 U cols), 4 warps (2x2), warp 64x64.
// In-register silu(G)*U. 2-stage bulk pipeline, 3 CTA/SM. y = y0 + blockIdx.y.
// ---------------------------------------------------------------------------
__global__ __launch_bounds__(128, 3) __cluster_dims__(1, 1, 1) void gemm1_kernel(int y0) {
    const int tile = blockIdx.x;
    const int e = g_tile_expert[tile];
    if (e < 0) return;
    const int y = y0 + blockIdx.y;     // 64-col block (== gemm2 k-chunk index)

    extern __shared__ __align__(128) char sh[];
    __shared__ __align__(8) unsigned long long mbars[NSTAGE];
    const uint32_t sb = smem_u32(sh);
    const uint32_t mb0 = smem_u32(mbars);
    const int tid = threadIdx.x;

    if (tid == 0)
        for (int s = 0; s < NSTAGE; s++) mbar_init(mb0 + 8 * s);
    __syncthreads();

    const __half* Asrc = g_xt  + (size_t)tile * 12 * 128 * LDH;
    const __half* Bsrc = g_wgu + (size_t)((e * 32 + y) * 12) * 128 * LDH;

    const int NK = DDIM / KC;  // 12
    if (tid == 0) {
        FENCE_ASYNC();
#pragma unroll
        for (int s = 0; s < NSTAGE; s++) {
            mbar_expect_tx(mb0 + 8 * s, STAGE_BYTES);
            bulk_g2s(sb + s * STAGE_BYTES,              Asrc + (size_t)s * 128 * LDH, TILE_BYTES, mb0 + 8 * s);
            bulk_g2s(sb + s * STAGE_BYTES + TILE_BYTES, Bsrc + (size_t)s * 128 * LDH, TILE_BYTES, mb0 + 8 * s);
        }
    }

    const int wid = tid >> 5, wm = wid >> 1, wn = wid & 1;
    wmma::fragment<wmma::accumulator, 16, 16, 16, float> acc[4][4];
#pragma unroll
    for (int i = 0; i < 4; i++)
#pragma unroll
        for (int j = 0; j < 4; j++) wmma::fill_fragment(acc[i][j], 0.0f);

    for (int kc = 0; kc < NK; kc++) {
        const int s = kc & 1;
        mbar_wait(mb0 + 8 * s, (kc >> 1) & 1);
        const __half* A = (const __half*)(sh + s * STAGE_BYTES);
        const __half* B = (const __half*)(sh + s * STAGE_BYTES + TILE_BYTES);
#pragma unroll
        for (int ks = 0; ks < KC / 16; ks++) {
            wmma::fragment<wmma::matrix_a, 16, 16, 16, __half, wmma::row_major> fa[4];
            wmma::fragment<wmma::matrix_b, 16, 16, 16, __half, wmma::col_major> fb[4];
#pragma unroll
            for (int i = 0; i < 4; i++)
                wmma::load_matrix_sync(fa[i], A + (wm * 64 + i * 16) * LDH + ks * 16, LDH);
#pragma unroll
            for (int j = 0; j < 4; j++)
                wmma::load_matrix_sync(fb[j], B + (wn * 64 + j * 16) * LDH + ks * 16, LDH);
#pragma unroll
            for (int i = 0; i < 4; i++)
#pragma unroll
                for (int j = 0; j < 4; j++)
                    wmma::mma_sync(acc[i][j], fa[i], fb[j], acc[i][j]);
        }
        __syncthreads();
        int kn = kc + NSTAGE;
        if (kn < NK && tid == 0) {
            mbar_expect_tx(mb0 + 8 * s, STAGE_BYTES);
            bulk_g2s(sb + s * STAGE_BYTES,              Asrc + (size_t)kn * 128 * LDH, TILE_BYTES, mb0 + 8 * s);
            bulk_g2s(sb + s * STAGE_BYTES + TILE_BYTES, Bsrc + (size_t)kn * 128 * LDH, TILE_BYTES, mb0 + 8 * s);
        }
    }

    // In-register silu(G)*U, stage fp32 h (128 x 64, stride 68), write fp16 tile
    float* st = (float*)sh;   // 128*68*4 = 34816 B <= 73728
    __syncthreads();
#pragma unroll
    for (int i = 0; i < 4; i++)
#pragma unroll
        for (int jj = 0; jj < 2; jj++) {
#pragma unroll
            for (int el = 0; el < acc[i][jj].num_elements; el++) {
                float g = acc[i][jj].x[el];
                float u = acc[i][jj + 2].x[el];
                acc[i][jj].x[el] = (g / (1.0f + __expf(-g))) * u;
            }
            wmma::store_matrix_sync(st + (wm * 64 + i * 16) * LDST2 + wn * 32 + jj * 16,
                                    acc[i][jj], LDST2, wmma::mem_row_major);
        }
    __syncthreads();

    __half* hdst = g_ht + (size_t)(tile * 32 + y) * 128 * LDH;
#pragma unroll
    for (int j = 0; j < 32; j++) {               // 128 rows x 32 half2 cols
        int p = tid + 128 * j;
        int r = p >> 5, c2 = p & 31;
        float h0 = st[r * LDST2 + c2 * 2];
        float h1 = st[r * LDST2 + c2 * 2 + 1];
        __half2 hv = __floats2half2_rn(h0, h1);
        *(uint32_t*)(hdst + r * LDH + c2 * 2) = *(uint32_t*)&hv;
    }
}

// ---------------------------------------------------------------------------
// GEMM2: one split-K half per launch (z param). 128x128 CTA, 4 warps, 64x64.
// ---------------------------------------------------------------------------
__global__ __launch_bounds__(128, 3) __cluster_dims__(1, 1, 1) void gemm2_kernel(int z) {
    const int tile = blockIdx.x;
    const int e = g_tile_expert[tile];
    if (e < 0) return;
    const int y = blockIdx.y;

    extern __shared__ __align__(128) char sh[];
    __shared__ __align__(8) unsigned long long mbars[NSTAGE];
    const uint32_t sb = smem_u32(sh);
    const uint32_t mb0 = smem_u32(mbars);
    const int tid = threadIdx.x;

    if (tid == 0)
        for (int s = 0; s < NSTAGE; s++) mbar_init(mb0 + 8 * s);
    __syncthreads();

    const __half* Asrc = g_ht  + (size_t)(tile * 32 + z * 16) * 128 * LDH;
    const __half* Bsrc = g_wdt + (size_t)((e * 6 + y) * 32 + z * 16) * 128 * LDH;

    const int NK = 16;
    if (tid == 0) {
        FENCE_ASYNC();
#pragma unroll
        for (int s = 0; s < NSTAGE; s++) {
            mbar_expect_tx(mb0 + 8 * s, STAGE_BYTES);
            bulk_g2s(sb + s * STAGE_BYTES,              Asrc + (size_t)s * 128 * LDH, TILE_BYTES, mb0 + 8 * s);
            bulk_g2s(sb + s * STAGE_BYTES + TILE_BYTES, Bsrc + (size_t)s * 128 * LDH, TILE_BYTES, mb0 + 8 * s);
        }
    }

    const int wid = tid >> 5, wm = wid >> 1, wn = wid & 1;
    wmma::fragment<wmma::accumulator, 16, 16, 16, float> acc[4][4];
#pragma unroll
    for (int i = 0; i < 4; i++)
#pragma unroll
        for (int j = 0; j < 4; j++) wmma::fill_fragment(acc[i][j], 0.0f);

    for (int kc = 0; kc < NK; kc++) {
        const int s = kc & 1;
        mbar_wait(mb0 + 8 * s, (kc >> 1) & 1);
        const __half* A = (const __half*)(sh + s * STAGE_BYTES);
        const __half* B = (const __half*)(sh + s * STAGE_BYTES + TILE_BYTES);
#pragma unroll
        for (int ks = 0; ks < KC / 16; ks++) {
            wmma::fragment<wmma::matrix_a, 16, 16, 16, __half, wmma::row_major> fa[4];
            wmma::fragment<wmma::matrix_b, 16, 16, 16, __half, wmma::col_major> fb[4];
#pragma unroll
            for (int i = 0; i < 4; i++)
                wmma::load_matrix_sync(fa[i], A + (wm * 64 + i * 16) * LDH + ks * 16, LDH);
#pragma unroll
            for (int j = 0; j < 4; j++)
                wmma::load_matrix_sync(fb[j], B + (wn * 64 + j * 16) * LDH + ks * 16, LDH);
#pragma unroll
            for (int i = 0; i < 4; i++)
#pragma unroll
                for (int j = 0; j < 4; j++)
                    wmma::mma_sync(acc[i][j], fa[i], fb[j], acc[i][j]);
        }
        __syncthreads();
        int kn = kc + NSTAGE;
        if (kn < NK && tid == 0) {
            mbar_expect_tx(mb0 + 8 * s, STAGE_BYTES);
            bulk_g2s(sb + s * STAGE_BYTES,              Asrc + (size_t)kn * 128 * LDH, TILE_BYTES, mb0 + 8 * s);
            bulk_g2s(sb + s * STAGE_BYTES + TILE_BYTES, Bsrc + (size_t)kn * 128 * LDH, TILE_BYTES, mb0 + 8 * s);
        }
    }

    // Stage fp32 (128 x 132), write partial (permuted order, no scatter).
    float* st = (float*)sh;
    __syncthreads();
#pragma unroll
    for (int i = 0; i < 4; i++)
#pragma unroll
        for (int j = 0; j < 4; j++)
            wmma::store_matrix_sync(st + (wm * 64 + i * 16) * LDST + wn * 64 + j * 16,
                                    acc[i][j], LDST, wmma::mem_row_major);
    __syncthreads();

    float* dst = g_gp + ((size_t)z * PADROWS + tile * 128) * DDIM + y * 128;
#pragma unroll
    for (int j = 0; j < 32; j++) {               // 128 rows x 32 float4 cols
        int p = tid + 128 * j;
        int r = p >> 5, c4 = (p & 31) * 4;
        *(float4*)(dst + (size_t)r * DDIM + c4) = *(float4*)&st[r * LDST + c4];
    }
}

// ---------------------------------------------------------------------------
// add partials + scatter to output
// ---------------------------------------------------------------------------
__global__ void add_kernel(float* __restrict__ out) {
    int idx = blockIdx.x * 256 + threadIdx.x;
    if (idx >= PADROWS * (DDIM / 4)) return;
    int p = idx / (DDIM / 4), c4 = (idx % (DDIM / 4)) * 4;
    int t = g_perm[p];
    if (t < 0) return;
    const float* a = g_gp + (size_t)p * DDIM + c4;
    const float* b = g_gp + (size_t)(PADROWS + p) * DDIM + c4;
    float4 va = *(const float4*)a, vb = *(const float4*)b;
    float4 o = make_float4(va.x + vb.x, va.y + vb.y, va.z + vb.z, va.w + vb.w);
    *(float4*)(out + (size_t)t * DDIM + c4) = o;
}

// ---------------------------------------------------------------------------
extern "C" void kernel_launch(void* const* d_in, const int* in_sizes, int n_in,
                              void* d_out, int out_size) {
    const float* x   = (const float*)d_in[0];
    const void*  pos = d_in[1];
    // d_in[2] = behavior_index: unused
    const float* gw  = (const float*)d_in[3];
    const float* uw  = (const float*)d_in[4];
    const float* dw  = (const float*)d_in[5];
    float* out = (float*)d_out;

    static cudaStream_t s2 = nullptr, s3 = nullptr;
    static cudaEvent_t eFork = nullptr, eW1 = nullptr, eW2 = nullptr,
                       eWd = nullptr, eG1a = nullptr, eZ0 = nullptr;
    if (!s2) {
        cudaStreamCreateWithFlags(&s2, cudaStreamNonBlocking);
        cudaStreamCreateWithFlags(&s3, cudaStreamNonBlocking);
        cudaEventCreateWithFlags(&eFork, cudaEventDisableTiming);
        cudaEventCreateWithFlags(&eW1, cudaEventDisableTiming);
        cudaEventCreateWithFlags(&eW2, cudaEventDisableTiming);
        cudaEventCreateWithFlags(&eWd, cudaEventDisableTiming);
        cudaEventCreateWithFlags(&eG1a, cudaEventDisableTiming);
        cudaEventCreateWithFlags(&eZ0, cudaEventDisableTiming);
        cudaFuncSetAttribute(gemm1_kernel, cudaFuncAttributeMaxDynamicSharedMemorySize, GSMEM);
        cudaFuncSetAttribute(gemm2_kernel, cudaFuncAttributeMaxDynamicSharedMemorySize, GSMEM);
    }

    const int WGU_HALF_BLOCKS = (NEXP * 16 * 12 * 128 * 9 + 255) / 256;

    // Fork
    cudaEventRecord(eFork, 0);
    cudaStreamWaitEvent(s2, eFork, 0);
    cudaStreamWaitEvent(s3, eFork, 0);

    // s2: gate/up conversion in two halves
    cvt_wgu<<<WGU_HALF_BLOCKS, 256, 0, s2>>>(gw, uw, 0);
    cudaEventRecord(eW1, s2);
    cvt_wgu<<<WGU_HALF_BLOCKS, 256, 0, s2>>>(gw, uw, 16);
    cudaEventRecord(eW2, s2);

    // s3: down-proj conversion
    cvt_wd<<<(NEXP * 6 * 32 * 128 * 9 + 255) / 256, 256, 0, s3>>>(dw);
    cudaEventRecord(eWd, s3);

    // main: routing + x conversion
    route_kernel<<<1, 1024>>>(pos);
    cvt_x<<<(NTILES * 12 * 128 * 9 + 255) / 256, 256>>>(x);

    // gemm1a: y 0-15 (needs route+cvt_x program order, cvt_wgu half 1)
    cudaStreamWaitEvent(0, eW1, 0);
    gemm1_kernel<<<dim3(NTILES, 16), 128, GSMEM>>>(0);
    cudaEventRecord(eG1a, 0);

    // s3: gemm2 z=0 (needs gemm1a + cvt_wd[s3 program order]) — overlaps gemm1b
    cudaStreamWaitEvent(s3, eG1a, 0);
    gemm2_kernel<<<dim3(NTILES, 6), 128, GSMEM, s3>>>(0);
    cudaEventRecord(eZ0, s3);

    // main: gemm1b y 16-31 (needs cvt_wgu half 2)
    cudaStreamWaitEvent(0, eW2, 0);
    gemm1_kernel<<<dim3(NTILES, 16), 128, GSMEM>>>(16);

    // main: gemm2 z=1 (needs gemm1b program order + cvt_wd)
    cudaStreamWaitEvent(0, eWd, 0);
    gemm2_kernel<<<dim3(NTILES, 6), 128, GSMEM>>>(1);

    // join + combine
    cudaStreamWaitEvent(0, eZ0, 0);
    add_kernel<<<(PADROWS * (DDIM / 4) + 255) / 256, 256>>>(out);
}

// round 12
// speedup vs baseline: 1.2387x; 1.1011x over previous
#include <cuda_runtime.h>
#include <cuda_fp16.h>
#include <mma.h>
#include <cstdint>

using namespace nvcuda;

#define T_TOK 4096
#define DDIM  768
#define IDIM  2048
#define NEXP  8
#define TM    128
#define NTILES 40
#define PADROWS (NTILES*TM)
#define KC    64             // halves per K chunk
#define LDH   72             // padded row length (halves): 144B rows, conflict-free ldmatrix
#define LDST  132            // fp32 staging stride (gemm2): %4==0, row %16B==0
#define LDST2 68             // fp32 staging stride (gemm1, 64 cols)
#define TILE_BYTES (128 * LDH * 2)       // 18432 B contiguous A or B chunk
#define STAGE_BYTES (2 * TILE_BYTES)     // 36864
#define NSTAGE 2
#define GSMEM (NSTAGE * STAGE_BYTES)     // 73728 -> 3 CTA/SM

// ---------------- device-global scratch (tiled layouts, no allocation) ------
__device__ int    g_perm[PADROWS];
__device__ int    g_tile_expert[NTILES];
// [e][y:32][kc:12][r:128][72]  rows interleaved [G0-31|U0-31|G32-63|U32-63]
__device__ __half g_wgu[(size_t)NEXP * 32 * 12 * 128 * LDH];
// [e][y:6][kc:32][r:128][72]
__device__ __half g_wdt[(size_t)NEXP * 6 * 32 * 128 * LDH];
// [tile:40][kc:12][r:128][72]
__device__ __half g_xt [(size_t)NTILES * 12 * 128 * LDH];
// [tile:40][kc:32][r:128][72]
__device__ __half g_ht [(size_t)NTILES * 32 * 128 * LDH];
// split-K partials, permuted row order: [z:2][PADROWS][768]
__device__ float  g_gp [(size_t)2 * PADROWS * DDIM];

// ---------------- PTX helpers -----------------------------------------------
__device__ __forceinline__ uint32_t smem_u32(const void* p) {
    uint32_t a;
    asm("{ .reg .u64 t; cvta.to.shared.u64 t, %1; cvt.u32.u64 %0, t; }" : "=r"(a) : "l"(p));
    return a;
}
__device__ __forceinline__ void mbar_init(uint32_t a) {
    asm volatile("mbarrier.init.shared.b64 [%0], 1;" :: "r"(a) : "memory");
}
__device__ __forceinline__ void mbar_expect_tx(uint32_t a, uint32_t bytes) {
    asm volatile("mbarrier.arrive.expect_tx.shared.b64 _, [%0], %1;" :: "r"(a), "r"(bytes) : "memory");
}
__device__ __forceinline__ void mbar_wait(uint32_t mbar, int parity) {
    asm volatile(
        "{\n\t.reg .pred P;\n\t"
        "WL_%=:\n\t"
        "mbarrier.try_wait.parity.acquire.cta.shared::cta.b64 P, [%0], %1, 0x989680;\n\t"
        "@P bra.uni WD_%=;\n\t"
        "bra.uni WL_%=;\n\t"
        "WD_%=:\n\t}"
        :: "r"(mbar), "r"(parity) : "memory");
}
__device__ __forceinline__ void bulk_g2s(uint32_t dst, const void* src, uint32_t bytes, uint32_t mbar) {
    asm volatile(
        "cp.async.bulk.shared::cluster.global.mbarrier::complete_tx::bytes [%0], [%1], %2, [%3];"
        :: "r"(dst), "l"(src), "r"(bytes), "r"(mbar) : "memory");
}
#define FENCE_ASYNC() asm volatile("fence.proxy.async.shared::cta;" ::: "memory")

// ---------------------------------------------------------------------------
// Routing (int64/int32 safe) — r9 version (proven; not on critical path)
// ---------------------------------------------------------------------------
__global__ void route_kernel(const void* __restrict__ pos) {
    __shared__ int cnt[NEXP], off[NEXP], cur[NEXP];
    __shared__ int s_not64;
    const int tid = threadIdx.x;
    if (tid < NEXP) { cnt[tid] = 0; cur[tid] = 0; }
    if (tid == 0) s_not64 = 0;
    __syncthreads();
    const unsigned long long* pl = (const unsigned long long*)pos;
    for (int i = tid; i < T_TOK / 2; i += blockDim.x)
        if (pl[i] > 7ULL) s_not64 = 1;
    __syncthreads();
    const int is64 = !s_not64;
    const long long* p64 = (const long long*)pos;
    const int*       p32 = (const int*)pos;
    for (int t = tid; t < T_TOK; t += blockDim.x) {
        int e = is64 ? (int)p64[t] : p32[t];
        atomicAdd(&cnt[e], 1);
    }
    for (int i = tid; i < PADROWS; i += blockDim.x) g_perm[i] = -1;
    __syncthreads();
    if (tid == 0) {
        int o = 0;
        for (int e = 0; e < NEXP; e++) {
            off[e] = o;
            int nt = (cnt[e] + TM - 1) / TM;
            for (int k = 0; k < nt; k++) g_tile_expert[o / TM + k] = e;
            o += nt * TM;
        }
        for (int tl = o / TM; tl < NTILES; tl++) g_tile_expert[tl] = -1;
    }
    __syncthreads();
    for (int t = tid; t < T_TOK; t += blockDim.x) {
        int e = is64 ? (int)p64[t] : p32[t];
        int p = off[e] + atomicAdd(&cur[e], 1);
        g_perm[p] = t;
    }
}

// ---------------------------------------------------------------------------
// cvt: fp32 -> fp16 into tiled layouts
// ---------------------------------------------------------------------------
__device__ __forceinline__ uint4 cvt8(const float* src) {
    float4 v0 = *(const float4*)src;
    float4 v1 = *(const float4*)(src + 4);
    __half2 h0 = __floats2half2_rn(v0.x, v0.y), h1 = __floats2half2_rn(v0.z, v0.w);
    __half2 h2 = __floats2half2_rn(v1.x, v1.y), h3 = __floats2half2_rn(v1.z, v1.w);
    uint4 o;
    o.x = *(uint32_t*)&h0; o.y = *(uint32_t*)&h1;
    o.z = *(uint32_t*)&h2; o.w = *(uint32_t*)&h3;
    return o;
}

// y-half of the gate/up interleaved layout: y in [y0, y0+16)  (r11-verified)
__global__ void cvt_wgu(const float* __restrict__ gw, const float* __restrict__ uw, int y0) {
    const int TOT = NEXP * 16 * 12 * 128 * 9;
    int idx = blockIdx.x * 256 + threadIdx.x;
    if (idx >= TOT) return;
    int c8 = idx % 9; int t1 = idx / 9;
    int r  = t1 % 128; t1 /= 128;
    int kc = t1 % 12;  t1 /= 12;
    int y  = y0 + (t1 % 16);  int e = t1 / 16;
    uint4 o = make_uint4(0, 0, 0, 0);
    if (c8 < 8) {
        int q = r & 63;
        int wrow = y * 64 + (r >> 6) * 32 + (q & 31);
        const float* src = ((q < 32) ? gw : uw) + ((size_t)e * IDIM + wrow) * DDIM + kc * 64 + c8 * 8;
        o = cvt8(src);
    }
    size_t dst = ((((size_t)(e * 32 + y) * 12 + kc) * 128 + r) * 9 + c8) * 8;
    *(uint4*)(g_wgu + dst) = o;
}

__global__ void cvt_wd(const float* __restrict__ dw) {
    const int TOT = NEXP * 6 * 32 * 128 * 9;
    int idx = blockIdx.x * 256 + threadIdx.x;
    if (idx >= TOT) return;
    int c8 = idx % 9; int t1 = idx / 9;
    int r  = t1 % 128; t1 /= 128;
    int kc = t1 % 32;  t1 /= 32;
    int y  = t1 % 6;   int e = t1 / 6;
    uint4 o = make_uint4(0, 0, 0, 0);
    if (c8 < 8) {
        const float* src = dw + ((size_t)e * DDIM + y * 128 + r) * IDIM + kc * 64 + c8 * 8;
        o = cvt8(src);
    }
    *(uint4*)(g_wdt + (size_t)idx * 8) = o;
}

__global__ void cvt_x(const float* __restrict__ x) {   // run AFTER route
    const int TOT = NTILES * 12 * 128 * 9;
    int idx = blockIdx.x * 256 + threadIdx.x;
    if (idx >= TOT) return;
    int c8 = idx % 9; int t1 = idx / 9;
    int r  = t1 % 128; t1 /= 128;
    int kc = t1 % 12;  int tile = t1 / 12;
    uint4 o = make_uint4(0, 0, 0, 0);
    int t = g_perm[tile * TM + r];
    if (c8 < 8 && t >= 0)
        o = cvt8(x + (size_t)t * DDIM + kc * 64 + c8 * 8);
    *(uint4*)(g_xt + (size_t)idx * 8) = o;
}

// ---------------------------------------------------------------------------
// GEMM1: 128x128 CTA tile (64 G cols + 64 U cols), 4 warps (2x2), warp 64x64.
// In-register silu(G)*U. 2-stage bulk pipeline, 3 CTA/SM.  (r9 exact)
// ---------------------------------------------------------------------------
__global__ __launch_bounds__(128, 3) __cluster_dims__(1, 1, 1) void gemm1_kernel() {
    const int tile = blockIdx.x;
    const int e = g_tile_expert[tile];
    if (e < 0) return;
    const int y = blockIdx.y;          // 64-col block (== gemm2 k-chunk index)

    extern __shared__ __align__(128) char sh[];
    __shared__ __align__(8) unsigned long long mbars[NSTAGE];
    const uint32_t sb = smem_u32(sh);
    const uint32_t mb0 = smem_u32(mbars);
    const int tid = threadIdx.x;

    if (tid == 0)
        for (int s = 0; s < NSTAGE; s++) mbar_init(mb0 + 8 * s);
    __syncthreads();

    const __half* Asrc = g_xt  + (size_t)tile * 12 * 128 * LDH;
    const __half* Bsrc = g_wgu + (size_t)((e * 32 + y) * 12) * 128 * LDH;

    const int NK = DDIM / KC;  // 12
    if (tid == 0) {
        FENCE_ASYNC();
#pragma unroll
        for (int s = 0; s < NSTAGE; s++) {
            mbar_expect_tx(mb0 + 8 * s, STAGE_BYTES);
            bulk_g2s(sb + s * STAGE_BYTES,              Asrc + (size_t)s * 128 * LDH, TILE_BYTES, mb0 + 8 * s);
            bulk_g2s(sb + s * STAGE_BYTES + TILE_BYTES, Bsrc + (size_t)s * 128 * LDH, TILE_BYTES, mb0 + 8 * s);
        }
    }

    const int wid = tid >> 5, wm = wid >> 1, wn = wid & 1;
    wmma::fragment<wmma::accumulator, 16, 16, 16, float> acc[4][4];
#pragma unroll
    for (int i = 0; i < 4; i++)
#pragma unroll
        for (int j = 0; j < 4; j++) wmma::fill_fragment(acc[i][j], 0.0f);

    for (int kc = 0; kc < NK; kc++) {
        const int s = kc & 1;
        mbar_wait(mb0 + 8 * s, (kc >> 1) & 1);
        const __half* A = (const __half*)(sh + s * STAGE_BYTES);
        const __half* B = (const __half*)(sh + s * STAGE_BYTES + TILE_BYTES);
#pragma unroll
        for (int ks = 0; ks < KC / 16; ks++) {
            wmma::fragment<wmma::matrix_a, 16, 16, 16, __half, wmma::row_major> fa[4];
            wmma::fragment<wmma::matrix_b, 16, 16, 16, __half, wmma::col_major> fb[4];
#pragma unroll
            for (int i = 0; i < 4; i++)
                wmma::load_matrix_sync(fa[i], A + (wm * 64 + i * 16) * LDH + ks * 16, LDH);
#pragma unroll
            for (int j = 0; j < 4; j++)
                wmma::load_matrix_sync(fb[j], B + (wn * 64 + j * 16) * LDH + ks * 16, LDH);
#pragma unroll
            for (int i = 0; i < 4; i++)
#pragma unroll
                for (int j = 0; j < 4; j++)
                    wmma::mma_sync(acc[i][j], fa[i], fb[j], acc[i][j]);
        }
        __syncthreads();
        int kn = kc + NSTAGE;
        if (kn < NK && tid == 0) {
            mbar_expect_tx(mb0 + 8 * s, STAGE_BYTES);
            bulk_g2s(sb + s * STAGE_BYTES,              Asrc + (size_t)kn * 128 * LDH, TILE_BYTES, mb0 + 8 * s);
            bulk_g2s(sb + s * STAGE_BYTES + TILE_BYTES, Bsrc + (size_t)kn * 128 * LDH, TILE_BYTES, mb0 + 8 * s);
        }
    }

    // In-register silu(G)*U, stage fp32 h (128 x 64, stride 68), write fp16 tile
    float* st = (float*)sh;   // 128*68*4 = 34816 B <= 73728
    __syncthreads();
#pragma unroll
    for (int i = 0; i < 4; i++)
#pragma unroll
        for (int jj = 0; jj < 2; jj++) {
#pragma unroll
            for (int el = 0; el < acc[i][jj].num_elements; el++) {
                float g = acc[i][jj].x[el];
                float u = acc[i][jj + 2].x[el];
                acc[i][jj].x[el] = (g / (1.0f + __expf(-g))) * u;
            }
            wmma::store_matrix_sync(st + (wm * 64 + i * 16) * LDST2 + wn * 32 + jj * 16,
                                    acc[i][jj], LDST2, wmma::mem_row_major);
        }
    __syncthreads();

    __half* hdst = g_ht + (size_t)(tile * 32 + y) * 128 * LDH;
#pragma unroll
    for (int j = 0; j < 32; j++) {               // 128 rows x 32 half2 cols
        int p = tid + 128 * j;
        int r = p >> 5, c2 = p & 31;
        float h0 = st[r * LDST2 + c2 * 2];
        float h1 = st[r * LDST2 + c2 * 2 + 1];
        __half2 hv = __floats2half2_rn(h0, h1);
        *(uint32_t*)(hdst + r * LDH + c2 * 2) = *(uint32_t*)&hv;
    }
}

// ---------------------------------------------------------------------------
// GEMM2: split-K (blockIdx.z). 128x128 CTA, 4 warps, 64x64.  (r9 exact)
// ---------------------------------------------------------------------------
__global__ __launch_bounds__(128, 3) __cluster_dims__(1, 1, 1) void gemm2_kernel() {
    const int tile = blockIdx.x;
    const int e = g_tile_expert[tile];
    if (e < 0) return;
    const int y = blockIdx.y;
    const int z = blockIdx.z;

    extern __shared__ __align__(128) char sh[];
    __shared__ __align__(8) unsigned long long mbars[NSTAGE];
    const uint32_t sb = smem_u32(sh);
    const uint32_t mb0 = smem_u32(mbars);
    const int tid = threadIdx.x;

    if (tid == 0)
        for (int s = 0; s < NSTAGE; s++) mbar_init(mb0 + 8 * s);
    __syncthreads();

    const __half* Asrc = g_ht  + (size_t)(tile * 32 + z * 16) * 128 * LDH;
    const __half* Bsrc = g_wdt + (size_t)((e * 6 + y) * 32 + z * 16) * 128 * LDH;

    const int NK = 16;
    if (tid == 0) {
        FENCE_ASYNC();
#pragma unroll
        for (int s = 0; s < NSTAGE; s++) {
            mbar_expect_tx(mb0 + 8 * s, STAGE_BYTES);
            bulk_g2s(sb + s * STAGE_BYTES,              Asrc + (size_t)s * 128 * LDH, TILE_BYTES, mb0 + 8 * s);
            bulk_g2s(sb + s * STAGE_BYTES + TILE_BYTES, Bsrc + (size_t)s * 128 * LDH, TILE_BYTES, mb0 + 8 * s);
        }
    }

    const int wid = tid >> 5, wm = wid >> 1, wn = wid & 1;
    wmma::fragment<wmma::accumulator, 16, 16, 16, float> acc[4][4];
#pragma unroll
    for (int i = 0; i < 4; i++)
#pragma unroll
        for (int j = 0; j < 4; j++) wmma::fill_fragment(acc[i][j], 0.0f);

    for (int kc = 0; kc < NK; kc++) {
        const int s = kc & 1;
        mbar_wait(mb0 + 8 * s, (kc >> 1) & 1);
        const __half* A = (const __half*)(sh + s * STAGE_BYTES);
        const __half* B = (const __half*)(sh + s * STAGE_BYTES + TILE_BYTES);
#pragma unroll
        for (int ks = 0; ks < KC / 16; ks++) {
            wmma::fragment<wmma::matrix_a, 16, 16, 16, __half, wmma::row_major> fa[4];
            wmma::fragment<wmma::matrix_b, 16, 16, 16, __half, wmma::col_major> fb[4];
#pragma unroll
            for (int i = 0; i < 4; i++)
                wmma::load_matrix_sync(fa[i], A + (wm * 64 + i * 16) * LDH + ks * 16, LDH);
#pragma unroll
            for (int j = 0; j < 4; j++)
                wmma::load_matrix_sync(fb[j], B + (wn * 64 + j * 16) * LDH + ks * 16, LDH);
#pragma unroll
            for (int i = 0; i < 4; i++)
#pragma unroll
                for (int j = 0; j < 4; j++)
                    wmma::mma_sync(acc[i][j], fa[i], fb[j], acc[i][j]);
        }
        __syncthreads();
        int kn = kc + NSTAGE;
        if (kn < NK && tid == 0) {
            mbar_expect_tx(mb0 + 8 * s, STAGE_BYTES);
            bulk_g2s(sb + s * STAGE_BYTES,              Asrc + (size_t)kn * 128 * LDH, TILE_BYTES, mb0 + 8 * s);
            bulk_g2s(sb + s * STAGE_BYTES + TILE_BYTES, Bsrc + (size_t)kn * 128 * LDH, TILE_BYTES, mb0 + 8 * s);
        }
    }

    // Stage fp32 (128 x 132), write partial (permuted order, no scatter).
    float* st = (float*)sh;
    __syncthreads();
#pragma unroll
    for (int i = 0; i < 4; i++)
#pragma unroll
        for (int j = 0; j < 4; j++)
            wmma::store_matrix_sync(st + (wm * 64 + i * 16) * LDST + wn * 64 + j * 16,
                                    acc[i][j], LDST, wmma::mem_row_major);
    __syncthreads();

    float* dst = g_gp + ((size_t)z * PADROWS + tile * 128) * DDIM + y * 128;
#pragma unroll
    for (int j = 0; j < 32; j++) {               // 128 rows x 32 float4 cols
        int p = tid + 128 * j;
        int r = p >> 5, c4 = (p & 31) * 4;
        *(float4*)(dst + (size_t)r * DDIM + c4) = *(float4*)&st[r * LDST + c4];
    }
}

// ---------------------------------------------------------------------------
// add partials + scatter to output
// ---------------------------------------------------------------------------
__global__ void add_kernel(float* __restrict__ out) {
    int idx = blockIdx.x * 256 + threadIdx.x;
    if (idx >= PADROWS * (DDIM / 4)) return;
    int p = idx / (DDIM / 4), c4 = (idx % (DDIM / 4)) * 4;
    int t = g_perm[p];
    if (t < 0) return;
    const float* a = g_gp + (size_t)p * DDIM + c4;
    const float* b = g_gp + (size_t)(PADROWS + p) * DDIM + c4;
    float4 va = *(const float4*)a, vb = *(const float4*)b;
    float4 o = make_float4(va.x + vb.x, va.y + vb.y, va.z + vb.z, va.w + vb.w);
    *(float4*)(out + (size_t)t * DDIM + c4) = o;
}

// ---------------------------------------------------------------------------
extern "C" void kernel_launch(void* const* d_in, const int* in_sizes, int n_in,
                              void* d_out, int out_size) {
    const float* x   = (const float*)d_in[0];
    const void*  pos = d_in[1];
    // d_in[2] = behavior_index: unused
    const float* gw  = (const float*)d_in[3];
    const float* uw  = (const float*)d_in[4];
    const float* dw  = (const float*)d_in[5];
    float* out = (float*)d_out;

    static cudaStream_t s2 = nullptr, s3 = nullptr;
    static cudaEvent_t eFork = nullptr, eWa = nullptr, eWb = nullptr, eWd = nullptr;
    if (!s2) {
        cudaStreamCreateWithFlags(&s2, cudaStreamNonBlocking);
        cudaStreamCreateWithFlags(&s3, cudaStreamNonBlocking);
        cudaEventCreateWithFlags(&eFork, cudaEventDisableTiming);
        cudaEventCreateWithFlags(&eWa, cudaEventDisableTiming);
        cudaEventCreateWithFlags(&eWb, cudaEventDisableTiming);
        cudaEventCreateWithFlags(&eWd, cudaEventDisableTiming);
        cudaFuncSetAttribute(gemm1_kernel, cudaFuncAttributeMaxDynamicSharedMemorySize, GSMEM);
        cudaFuncSetAttribute(gemm2_kernel, cudaFuncAttributeMaxDynamicSharedMemorySize, GSMEM);
    }

    const int WGU_HALF_BLOCKS = (NEXP * 16 * 12 * 128 * 9 + 255) / 256;

    // Fork: both weight-conversion streams start immediately.
    cudaEventRecord(eFork, 0);
    cudaStreamWaitEvent(s2, eFork, 0);
    cudaStreamWaitEvent(s3, eFork, 0);

    // s2: gate/up conversion, y 0-15
    cvt_wgu<<<WGU_HALF_BLOCKS, 256, 0, s2>>>(gw, uw, 0);
    cudaEventRecord(eWa, s2);

    // s3: gate/up conversion y 16-31, then down-proj conversion
    cvt_wgu<<<WGU_HALF_BLOCKS, 256, 0, s3>>>(gw, uw, 16);
    cudaEventRecord(eWb, s3);
    cvt_wd<<<(NEXP * 6 * 32 * 128 * 9 + 255) / 256, 256, 0, s3>>>(dw);
    cudaEventRecord(eWd, s3);

    // main: routing + x conversion (concurrent with weight conversions)
    route_kernel<<<1, 256>>>(pos);
    cvt_x<<<(NTILES * 12 * 128 * 9 + 255) / 256, 256>>>(x);

    // gemm1 (full grid): needs route+cvt_x (program order) + both wgu halves
    cudaStreamWaitEvent(0, eWa, 0);
    cudaStreamWaitEvent(0, eWb, 0);
    gemm1_kernel<<<dim3(NTILES, 32), 128, GSMEM>>>();

    // gemm2: needs gemm1 (program order) + cvt_wd (hidden under gemm1)
    cudaStreamWaitEvent(0, eWd, 0);
    gemm2_kernel<<<dim3(NTILES, 6, 2), 128, GSMEM>>>();
    add_kernel<<<(PADROWS * (DDIM / 4) + 255) / 256, 256>>>(out);
}